// round 1
// baseline (speedup 1.0000x reference)
#include <cuda_runtime.h>

#define GSZ   52
#define NANCH 3
#define NCELL (GSZ * GSZ * NANCH)   // 8112
#define REC   85
#define CLS   80
#define MAXB  64
#define MAXGT 64
#define IMGSZ 416.0f
#define RATIO 8.0f                  // 416/52, exact power of two

// ---- scratch (device globals; no allocation allowed) ----
__device__ float4 g_gt[MAXB][MAXGT];
__device__ int    g_cnt[MAXB];
__device__ double g_acc[5];  // txty, twth, noobj_conf, obj_conf, class (raw sums)

__device__ __forceinline__ float softplusf(float x) {
    // jax.nn.softplus == logaddexp(x, 0) == max(x,0) + log1p(exp(-|x|))
    return fmaxf(x, 0.0f) + log1pf(expf(-fabsf(x)));
}

__device__ __forceinline__ float sigmoidf_(float x) {
    return 1.0f / (1.0f + expf(-x));
}

__global__ void k_init() {
    int i = threadIdx.x;
    if (i < MAXB) g_cnt[i] = 0;
    if (i < 5)    g_acc[i] = 0.0;
}

// Kernel 1: scan all cells; obj cells -> append GT box, accumulate obj losses.
__global__ void k_obj(const float* __restrict__ preds,
                      const float* __restrict__ targets,
                      const float* __restrict__ anchors,
                      int B) {
    int tid = blockIdx.x * blockDim.x + threadIdx.x;
    int total = B * NCELL;
    if (tid >= total) return;

    int b = tid / NCELL;
    int n = tid - b * NCELL;

    const float* t = targets + (size_t)tid * REC;
    float conf = t[4];
    if (conf <= 0.0f) return;

    int a    = n % 3;
    int cell = n / 3;
    float fgx = (float)(cell % GSZ);   // offset_x = column index
    float fgy = (float)(cell / GSZ);   // offset_y = row index

    float tx = t[0], ty = t[1], tw = t[2], th = t[3];

    int slot = atomicAdd(&g_cnt[b], 1);
    if (slot < MAXGT) g_gt[b][slot] = make_float4(tx, ty, tw, th);

    const float* p = preds + (size_t)tid * REC;
    float aw = anchors[a * 2 + 0];
    float ah = anchors[a * 2 + 1];

    float rx = p[0], ry = p[1], rw = p[2], rh = p[3], rc = p[4];

    // replicate reference arithmetic order
    float sx = sigmoidf_(rx), sy = sigmoidf_(ry);
    float bx = (sx + fgx) * RATIO;
    float by = (sy + fgy) * RATIO;
    float pxn = bx / RATIO - fgx;
    float pyn = by / RATIO - fgy;
    float txn = tx / RATIO - fgx;
    float tyn = ty / RATIO - fgy;

    float scale = 2.0f - ((tw / IMGSZ) * th) / IMGSZ;

    float dx = pxn - txn, dy = pyn - tyn;
    float txty = (dx * dx) * scale + (dy * dy) * scale;

    float bw = expf(rw) * aw, bh = expf(rh) * ah;
    float pwn = bw / aw, phn = bh / ah;
    float twn = tw / aw, thn = th / ah;
    twn = (twn == 0.0f) ? 1.0f : twn;
    thn = (thn == 0.0f) ? 1.0f : thn;
    pwn = (pwn == 0.0f) ? 1.0f : pwn;
    phn = (phn == 0.0f) ? 1.0f : phn;
    twn = logf(fminf(fmaxf(twn, 1e-9f), 1e9f));
    thn = logf(fminf(fmaxf(thn, 1e-9f), 1e9f));
    pwn = logf(fminf(fmaxf(pwn, 1e-9f), 1e9f));
    phn = logf(fminf(fmaxf(phn, 1e-9f), 1e9f));
    float dw = pwn - twn, dh = phn - thn;
    float twth = (dw * dw) * scale + (dh * dh) * scale;

    float objc = softplusf(rc) - rc * conf;

    float clsl = 0.0f;
    #pragma unroll 8
    for (int c = 0; c < CLS; c++) {
        float x  = p[5 + c];
        float tc = t[5 + c];
        clsl += softplusf(x) - x * tc;
    }

    atomicAdd(&g_acc[0], (double)txty);
    atomicAdd(&g_acc[1], (double)twth);
    atomicAdd(&g_acc[3], (double)objc);
    atomicAdd(&g_acc[4], (double)clsl);
}

// Kernel 2: noobj conf loss. One block handles 256 cells of one batch.
__global__ void k_noobj(const float* __restrict__ preds,
                        const float* __restrict__ targets,
                        const float* __restrict__ anchors) {
    __shared__ float4 sgt[MAXGT];
    __shared__ int    scnt;
    __shared__ float  sanch[6];
    __shared__ float  sred[8];

    int b = blockIdx.y;
    if (threadIdx.x == 0) scnt = min(g_cnt[b], MAXGT);
    if (threadIdx.x < 6)  sanch[threadIdx.x] = anchors[threadIdx.x];
    if (threadIdx.x < MAXGT) sgt[threadIdx.x] = g_gt[b][threadIdx.x];
    __syncthreads();

    int n = blockIdx.x * blockDim.x + threadIdx.x;
    float contrib = 0.0f;

    if (n < NCELL) {
        size_t idx = ((size_t)b * NCELL + n) * REC;
        float conf_t = targets[idx + 4];
        if (conf_t <= 0.0f) {
            const float* p = preds + idx;
            float rx = p[0], ry = p[1], rw = p[2], rh = p[3], rc = p[4];
            int a    = n % 3;
            int cell = n / 3;
            float fgx = (float)(cell % GSZ);
            float fgy = (float)(cell / GSZ);

            float sx = sigmoidf_(rx), sy = sigmoidf_(ry);
            float bx = (sx + fgx) * RATIO;
            float by = (sy + fgy) * RATIO;
            float bw = expf(rw) * sanch[a * 2 + 0];
            float bh = expf(rh) * sanch[a * 2 + 1];

            float px0 = bx - bw * 0.5f, px1 = bx + bw * 0.5f;
            float py0 = by - bh * 0.5f, py1 = by + bh * 0.5f;
            float area_p = bw * bh;

            float best = 0.0f;
            int cnt = scnt;
            for (int i = 0; i < cnt; i++) {
                float4 g = sgt[i];
                float gx0 = g.x - g.z * 0.5f, gx1 = g.x + g.z * 0.5f;
                float gy0 = g.y - g.w * 0.5f, gy1 = g.y + g.w * 0.5f;
                float iw = fmaxf(fminf(px1, gx1) - fmaxf(px0, gx0), 0.0f);
                float ih = fmaxf(fminf(py1, gy1) - fmaxf(py0, gy0), 0.0f);
                float inter = iw * ih;
                float iou = inter / (area_p + g.z * g.w - inter + 1e-9f);
                best = fmaxf(best, iou);
            }
            if (best < 0.6f) contrib = softplusf(rc) - rc * conf_t;
        }
    }

    // block reduction (warp shuffle + smem)
    unsigned mask = 0xFFFFFFFFu;
    #pragma unroll
    for (int off = 16; off > 0; off >>= 1)
        contrib += __shfl_down_sync(mask, contrib, off);
    int lane = threadIdx.x & 31;
    int wid  = threadIdx.x >> 5;
    if (lane == 0) sred[wid] = contrib;
    __syncthreads();
    if (wid == 0) {
        float v = (lane < (blockDim.x >> 5)) ? sred[lane] : 0.0f;
        #pragma unroll
        for (int off = 4; off > 0; off >>= 1)
            v += __shfl_down_sync(mask, v, off);
        if (lane == 0) atomicAdd(&g_acc[2], (double)v);
    }
}

__global__ void k_final(float* __restrict__ out, int B) {
    if (threadIdx.x == 0 && blockIdx.x == 0) {
        float inv = 1.0f; // divide per reference: sum / B
        (void)inv;
        float v0 = (float)(g_acc[0] / (double)B);
        float v1 = (float)(g_acc[1] / (double)B);
        float v2 = (float)(g_acc[2] / (double)B);
        float v3 = (float)(g_acc[3] / (double)B);
        float v4 = (float)(g_acc[4] / (double)B);
        out[0] = v0;
        out[1] = v1;
        out[2] = v2;
        out[3] = v3;
        out[4] = v4;
        out[5] = (((v0 + v1) + v2) + v3) + v4;  // left-assoc like reference
    }
}

extern "C" void kernel_launch(void* const* d_in, const int* in_sizes, int n_in,
                              void* d_out, int out_size) {
    const float* preds   = (const float*)d_in[0];
    const float* targets = (const float*)d_in[1];
    const float* anchors = (const float*)d_in[2];
    float* out = (float*)d_out;

    int B = in_sizes[0] / (GSZ * GSZ * NANCH * REC);
    if (B > MAXB) B = MAXB;

    k_init<<<1, 64>>>();

    int total = B * NCELL;
    int threads = 256;
    int blocks = (total + threads - 1) / threads;
    k_obj<<<blocks, threads>>>(preds, targets, anchors, B);

    dim3 grid2((NCELL + threads - 1) / threads, B);
    k_noobj<<<grid2, threads>>>(preds, targets, anchors);

    k_final<<<1, 1>>>(out, B);
}

// round 2
// speedup vs baseline: 1.2492x; 1.2492x over previous
#include <cuda_runtime.h>

#define GSZ   52
#define NANCH 3
#define NCELL (GSZ * GSZ * NANCH)   // 8112
#define REC   85
#define CLS   80
#define MAXB  64
#define MAXGT 64
#define IMGSZ 416.0f
#define RATIO 8.0f
#define BPB   32                    // blocks per batch (ceil(8112/256))

// ---- scratch (device globals; zero-initialized at module load) ----
__device__ float4   g_gt[MAXB][MAXGT];
__device__ int      g_cnt[MAXB];
__device__ unsigned g_mask[MAXB * 256];     // ballot words, 32 cells each
__device__ float    g_pA[4][MAXB * BPB];    // txty, twth, objc, cls partials
__device__ float    g_pB[MAXB * BPB];       // noobj partials
__device__ unsigned g_done;

__device__ __forceinline__ float softplusf(float x) {
    return fmaxf(x, 0.0f) + log1pf(expf(-fabsf(x)));
}
__device__ __forceinline__ float sigmoidf_(float x) {
    return 1.0f / (1.0f + expf(-x));
}

// select 5 consecutive floats starting at offset k (0..3) from two float4s
__device__ __forceinline__ void select5(int k, float4 v0, float4 v1, float* o) {
    switch (k) {
        case 0: o[0]=v0.x; o[1]=v0.y; o[2]=v0.z; o[3]=v0.w; o[4]=v1.x; break;
        case 1: o[0]=v0.y; o[1]=v0.z; o[2]=v0.w; o[3]=v1.x; o[4]=v1.y; break;
        case 2: o[0]=v0.z; o[1]=v0.w; o[2]=v1.x; o[3]=v1.y; o[4]=v1.z; break;
        default:o[0]=v0.w; o[1]=v1.x; o[2]=v1.y; o[3]=v1.z; o[4]=v1.w; break;
    }
}

__device__ __forceinline__ float warpRedF(float v) {
    #pragma unroll
    for (int o = 16; o > 0; o >>= 1) v += __shfl_down_sync(0xffffffffu, v, o);
    return v;
}

// ============ Kernel A: conf scan, obj-mask ballot, GT gather, obj losses ===
__global__ void __launch_bounds__(256) kA(const float* __restrict__ preds,
                                          const float* __restrict__ targets,
                                          const float* __restrict__ anchors) {
    int b   = blockIdx.y;
    int tid = threadIdx.x;
    int n   = blockIdx.x * 256 + tid;
    bool active = n < NCELL;

    size_t rec = (size_t)b * NCELL + n;
    float conf = 0.0f;
    if (active) conf = __ldg(targets + rec * REC + 4);

    unsigned bal = __ballot_sync(0xffffffffu, conf > 0.0f);
    if ((tid & 31) == 0) g_mask[b * 256 + (n >> 5)] = bal;

    float txty = 0.f, twth = 0.f, objc = 0.f, clsl = 0.f;

    if (conf > 0.0f) {
        int a    = n % 3;
        int cell = n / 3;
        float fgx = (float)(cell % GSZ);
        float fgy = (float)(cell / GSZ);

        int slot = atomicAdd(&g_cnt[b], 1);

        // vectorized front loads: floats [85r, 85r+5)
        int k = (int)(rec & 3);
        size_t f  = rec * (size_t)REC;
        size_t a4 = (f - k) >> 2;
        float4 pv0 = __ldg((const float4*)preds   + a4);
        float4 pv1 = __ldg((const float4*)preds   + a4 + 1);
        float4 tv0 = __ldg((const float4*)targets + a4);
        float4 tv1 = __ldg((const float4*)targets + a4 + 1);
        float p5[5], t5[5];
        select5(k, pv0, pv1, p5);
        select5(k, tv0, tv1, t5);

        float tx = t5[0], ty = t5[1], tw = t5[2], th = t5[3];
        if (slot < MAXGT) g_gt[b][slot] = make_float4(tx, ty, tw, th);

        float aw = __ldg(anchors + a * 2 + 0);
        float ah = __ldg(anchors + a * 2 + 1);
        float rx = p5[0], ry = p5[1], rw = p5[2], rh = p5[3], rc = p5[4];

        float sx = sigmoidf_(rx), sy = sigmoidf_(ry);
        float bx = (sx + fgx) * RATIO;
        float by = (sy + fgy) * RATIO;
        float pxn = bx / RATIO - fgx;
        float pyn = by / RATIO - fgy;
        float txn = tx / RATIO - fgx;
        float tyn = ty / RATIO - fgy;
        float scale = 2.0f - ((tw / IMGSZ) * th) / IMGSZ;
        float dx = pxn - txn, dy = pyn - tyn;
        txty = (dx * dx) * scale + (dy * dy) * scale;

        float bw = expf(rw) * aw, bh = expf(rh) * ah;
        float pwn = bw / aw, phn = bh / ah;
        float twn = tw / aw, thn = th / ah;
        twn = (twn == 0.0f) ? 1.0f : twn;
        thn = (thn == 0.0f) ? 1.0f : thn;
        pwn = (pwn == 0.0f) ? 1.0f : pwn;
        phn = (phn == 0.0f) ? 1.0f : phn;
        twn = logf(fminf(fmaxf(twn, 1e-9f), 1e9f));
        thn = logf(fminf(fmaxf(thn, 1e-9f), 1e9f));
        pwn = logf(fminf(fmaxf(pwn, 1e-9f), 1e9f));
        phn = logf(fminf(fmaxf(phn, 1e-9f), 1e9f));
        float dw = pwn - twn, dh = phn - thn;
        twth = (dw * dw) * scale + (dh * dh) * scale;

        objc = softplusf(rc) - rc * conf;

        const float* prec = preds   + f;
        const float* trec = targets + f;
        #pragma unroll 4
        for (int c = 5; c < 85; c++) {
            float x  = __ldg(prec + c);
            float tc = __ldg(trec + c);
            clsl += softplusf(x) - x * tc;
        }
    }

    // block reduce 4 values
    __shared__ float sred[8][4];
    int lane = tid & 31, wid = tid >> 5;
    txty = warpRedF(txty); twth = warpRedF(twth);
    objc = warpRedF(objc); clsl = warpRedF(clsl);
    if (lane == 0) { sred[wid][0]=txty; sred[wid][1]=twth; sred[wid][2]=objc; sred[wid][3]=clsl; }
    __syncthreads();
    if (wid == 0) {
        float v0 = (lane < 8) ? sred[lane][0] : 0.f;
        float v1 = (lane < 8) ? sred[lane][1] : 0.f;
        float v2 = (lane < 8) ? sred[lane][2] : 0.f;
        float v3 = (lane < 8) ? sred[lane][3] : 0.f;
        #pragma unroll
        for (int o = 4; o > 0; o >>= 1) {
            v0 += __shfl_down_sync(0xffffffffu, v0, o);
            v1 += __shfl_down_sync(0xffffffffu, v1, o);
            v2 += __shfl_down_sync(0xffffffffu, v2, o);
            v3 += __shfl_down_sync(0xffffffffu, v3, o);
        }
        if (lane == 0) {
            int pb = b * BPB + blockIdx.x;
            g_pA[0][pb] = v0; g_pA[1][pb] = v1; g_pA[2][pb] = v2; g_pA[3][pb] = v3;
        }
    }
}

// ============ Kernel B: noobj loss + final reduction (last block) ===========
__global__ void __launch_bounds__(256) kB(const float* __restrict__ preds,
                                          const float* __restrict__ anchors,
                                          float* __restrict__ out, int B) {
    __shared__ float4 sbox[MAXGT];
    __shared__ float  sA[MAXGT];
    __shared__ float  sanch[6];
    __shared__ int    scnt;
    __shared__ float  sred[8];

    int b   = blockIdx.y;
    int tid = threadIdx.x;
    if (tid == 0) scnt = min(g_cnt[b], MAXGT);
    if (tid < 6)  sanch[tid] = anchors[tid];
    __syncthreads();
    int cnt = scnt;
    if (tid < cnt) {
        float4 g = g_gt[b][tid];
        sbox[tid] = make_float4(g.x - 0.5f * g.z, g.y - 0.5f * g.w,
                                g.x + 0.5f * g.z, g.y + 0.5f * g.w);
        sA[tid] = g.z * g.w + 1e-9f;
    }
    __syncthreads();

    int n = blockIdx.x * 256 + tid;
    float contrib = 0.0f;

    if (n < NCELL) {
        unsigned w = g_mask[b * 256 + (n >> 5)];      // broadcast within warp
        bool isobj = (w >> (n & 31)) & 1u;
        if (!isobj) {
            size_t rec = (size_t)b * NCELL + n;
            int k = (int)(rec & 3);
            size_t f  = rec * (size_t)REC;
            size_t a4 = (f - k) >> 2;
            float4 v0 = __ldg((const float4*)preds + a4);
            float4 v1 = __ldg((const float4*)preds + a4 + 1);
            float p5[5];
            select5(k, v0, v1, p5);

            int a    = n % 3;
            int cell = n / 3;
            float fgx = (float)(cell % GSZ);
            float fgy = (float)(cell / GSZ);

            float sx = sigmoidf_(p5[0]), sy = sigmoidf_(p5[1]);
            float bx = (sx + fgx) * RATIO;
            float by = (sy + fgy) * RATIO;
            float bw = expf(p5[2]) * sanch[a * 2 + 0];
            float bh = expf(p5[3]) * sanch[a * 2 + 1];

            float px0 = bx - bw * 0.5f, px1 = bx + bw * 0.5f;
            float py0 = by - bh * 0.5f, py1 = by + bh * 0.5f;
            float area_p = bw * bh;

            bool hit = false;
            for (int i = 0; i < cnt; i++) {
                float4 g = sbox[i];
                float iw = fminf(px1, g.z) - fmaxf(px0, g.x);
                float ih = fminf(py1, g.w) - fmaxf(py0, g.y);
                iw = fmaxf(iw, 0.0f); ih = fmaxf(ih, 0.0f);
                float inter = iw * ih;
                float s = area_p + sA[i];              // areap + areag + 1e-9
                // iou >= 0.6  <=>  inter >= 0.6*(s - inter)   (denom > 0)
                hit = hit | (inter >= 0.6f * (s - inter));
            }
            if (!hit) contrib = softplusf(p5[4]);      // conf_t == 0 here
        }
    }

    // block reduce noobj contribution
    int lane = tid & 31, wid = tid >> 5;
    contrib = warpRedF(contrib);
    if (lane == 0) sred[wid] = contrib;
    __syncthreads();
    if (wid == 0) {
        float v = (lane < 8) ? sred[lane] : 0.f;
        #pragma unroll
        for (int o = 4; o > 0; o >>= 1) v += __shfl_down_sync(0xffffffffu, v, o);
        if (lane == 0) g_pB[b * BPB + blockIdx.x] = v;
    }

    // ---- last-block final reduction ----
    __threadfence();
    __shared__ bool amLast;
    if (tid == 0) {
        unsigned v = atomicAdd(&g_done, 1u);
        amLast = (v == gridDim.x * gridDim.y - 1);
    }
    __syncthreads();
    if (!amLast) return;

    int nb = BPB * B;
    double s0 = 0, s1 = 0, s2 = 0, s3 = 0, s4 = 0;
    for (int i = tid; i < nb; i += 256) {
        s0 += (double)g_pA[0][i];
        s1 += (double)g_pA[1][i];
        s3 += (double)g_pA[2][i];
        s4 += (double)g_pA[3][i];
        s2 += (double)g_pB[i];
    }
    __shared__ double sw[8];
    double vals[5] = {s0, s1, s2, s3, s4};
    double res[5];
    #pragma unroll
    for (int j = 0; j < 5; j++) {
        double v = vals[j];
        #pragma unroll
        for (int o = 16; o > 0; o >>= 1) v += __shfl_down_sync(0xffffffffu, v, o);
        if (lane == 0) sw[wid] = v;
        __syncthreads();
        v = (tid < 8) ? sw[tid] : 0.0;
        if (wid == 0) {
            #pragma unroll
            for (int o = 4; o > 0; o >>= 1) v += __shfl_down_sync(0xffffffffu, v, o);
        }
        res[j] = v;
        __syncthreads();
    }
    if (tid == 0) {
        float v0 = (float)(res[0] / (double)B);
        float v1 = (float)(res[1] / (double)B);
        float v2 = (float)(res[2] / (double)B);
        float v3 = (float)(res[3] / (double)B);
        float v4 = (float)(res[4] / (double)B);
        out[0] = v0; out[1] = v1; out[2] = v2; out[3] = v3; out[4] = v4;
        out[5] = (((v0 + v1) + v2) + v3) + v4;
        g_done = 0;
    }
    if (tid < MAXB) g_cnt[tid] = 0;   // reset for next replay
}

extern "C" void kernel_launch(void* const* d_in, const int* in_sizes, int n_in,
                              void* d_out, int out_size) {
    const float* preds   = (const float*)d_in[0];
    const float* targets = (const float*)d_in[1];
    const float* anchors = (const float*)d_in[2];
    float* out = (float*)d_out;

    int B = in_sizes[0] / (NCELL * REC);
    if (B > MAXB) B = MAXB;

    dim3 grid(BPB, B);
    kA<<<grid, 256>>>(preds, targets, anchors);
    kB<<<grid, 256>>>(preds, anchors, out, B);
}

// round 3
// speedup vs baseline: 1.8972x; 1.5187x over previous
#include <cuda_runtime.h>

#define GSZ   52
#define NANCH 3
#define NCELL (GSZ * GSZ * NANCH)   // 8112
#define REC   85
#define MAXB  64
#define MAXGT 64
#define IMGSZ 416.0f
#define RATIO 8.0f
#define BPB   32        // kA blocks per batch (32*256 >= 8112)
#define TX    8
#define TY    8
#define TILES 7         // ceil(52/8)
#define NTILE (TILES * TILES)   // 49
#define KBT   192       // kB threads: 8*8 cells * 3 anchors
#define KCBX  8         // kC grid.x (8 warps/block -> 64 slots)

// ---- scratch (device globals; zero-init at load) ----
__device__ float4   g_gt[MAXB][MAXGT];
__device__ int      g_idx[MAXB][MAXGT];
__device__ int      g_cnt[MAXB];
__device__ unsigned g_mask[MAXB * 256];
__device__ float    g_pA[4][MAXB * KCBX];   // txty, twth, objc, cls
__device__ float    g_pB[MAXB * NTILE];     // noobj
__device__ unsigned g_done;

__device__ __forceinline__ float softplusf(float x) {
    return fmaxf(x, 0.0f) + log1pf(expf(-fabsf(x)));
}
__device__ __forceinline__ float sigmoidf_(float x) {
    return 1.0f / (1.0f + expf(-x));
}
__device__ __forceinline__ void select5(int k, float4 v0, float4 v1, float* o) {
    switch (k) {
        case 0: o[0]=v0.x; o[1]=v0.y; o[2]=v0.z; o[3]=v0.w; o[4]=v1.x; break;
        case 1: o[0]=v0.y; o[1]=v0.z; o[2]=v0.w; o[3]=v1.x; o[4]=v1.y; break;
        case 2: o[0]=v0.z; o[1]=v0.w; o[2]=v1.x; o[3]=v1.y; o[4]=v1.z; break;
        default:o[0]=v0.w; o[1]=v1.x; o[2]=v1.y; o[3]=v1.z; o[4]=v1.w; break;
    }
}
__device__ __forceinline__ float warpRedF(float v) {
    #pragma unroll
    for (int o = 16; o > 0; o >>= 1) v += __shfl_down_sync(0xffffffffu, v, o);
    return v;
}

// ===== kA: conf scan -> ballot mask + GT gather (no loss math) =====
__global__ void __launch_bounds__(256) kA(const float* __restrict__ targets) {
    int b = blockIdx.y;
    int n = blockIdx.x * 256 + threadIdx.x;
    float conf = 0.0f;
    size_t rec = (size_t)b * NCELL + n;
    if (n < NCELL) conf = __ldg(targets + rec * REC + 4);
    unsigned bal = __ballot_sync(0xffffffffu, conf > 0.0f);
    if ((threadIdx.x & 31) == 0) g_mask[b * 256 + (n >> 5)] = bal;
    if (conf > 0.0f) {
        int slot = atomicAdd(&g_cnt[b], 1);
        if (slot < MAXGT) {
            const float* r = targets + rec * REC;
            g_gt[b][slot]  = make_float4(__ldg(r), __ldg(r+1), __ldg(r+2), __ldg(r+3));
            g_idx[b][slot] = n;
        }
    }
}

// ===== kC: obj losses, one warp per GT slot =====
__global__ void __launch_bounds__(256) kC(const float* __restrict__ preds,
                                          const float* __restrict__ targets,
                                          const float* __restrict__ anchors) {
    int b = blockIdx.y, tid = threadIdx.x;
    int lane = tid & 31, wid = tid >> 5;
    int slot = blockIdx.x * 8 + wid;
    int cnt = min(g_cnt[b], MAXGT);

    float txty = 0.f, twth = 0.f, objc = 0.f, clsl = 0.f;

    if (slot < cnt) {
        int n = g_idx[b][slot];
        size_t f = ((size_t)b * NCELL + n) * REC;
        const float* p = preds + f;
        const float* t = targets + f;

        for (int c = 5 + lane; c < REC; c += 32) {
            float x = __ldg(p + c), tc = __ldg(t + c);
            clsl += softplusf(x) - x * tc;
        }

        if (lane == 0) {
            int a    = n % 3;
            int cell = n / 3;
            float fgx = (float)(cell % GSZ);
            float fgy = (float)(cell / GSZ);
            float aw = __ldg(anchors + a * 2 + 0);
            float ah = __ldg(anchors + a * 2 + 1);

            float rx = __ldg(p), ry = __ldg(p+1), rw = __ldg(p+2), rh = __ldg(p+3), rc = __ldg(p+4);
            float tx = __ldg(t), ty = __ldg(t+1), tw = __ldg(t+2), th = __ldg(t+3), conf = __ldg(t+4);

            float sx = sigmoidf_(rx), sy = sigmoidf_(ry);
            float bx = (sx + fgx) * RATIO;
            float by = (sy + fgy) * RATIO;
            float pxn = bx / RATIO - fgx;
            float pyn = by / RATIO - fgy;
            float txn = tx / RATIO - fgx;
            float tyn = ty / RATIO - fgy;
            float scale = 2.0f - ((tw / IMGSZ) * th) / IMGSZ;
            float dx = pxn - txn, dy = pyn - tyn;
            txty = (dx * dx) * scale + (dy * dy) * scale;

            float bw = expf(rw) * aw, bh = expf(rh) * ah;
            float pwn = bw / aw, phn = bh / ah;
            float twn = tw / aw, thn = th / ah;
            twn = (twn == 0.0f) ? 1.0f : twn;
            thn = (thn == 0.0f) ? 1.0f : thn;
            pwn = (pwn == 0.0f) ? 1.0f : pwn;
            phn = (phn == 0.0f) ? 1.0f : phn;
            twn = logf(fminf(fmaxf(twn, 1e-9f), 1e9f));
            thn = logf(fminf(fmaxf(thn, 1e-9f), 1e9f));
            pwn = logf(fminf(fmaxf(pwn, 1e-9f), 1e9f));
            phn = logf(fminf(fmaxf(phn, 1e-9f), 1e9f));
            float dw = pwn - twn, dh = phn - thn;
            twth = (dw * dw) * scale + (dh * dh) * scale;

            objc = softplusf(rc) - rc * conf;
        }
    }

    __shared__ float sred[8][4];
    txty = warpRedF(txty); twth = warpRedF(twth);
    objc = warpRedF(objc); clsl = warpRedF(clsl);
    if (lane == 0) { sred[wid][0]=txty; sred[wid][1]=twth; sred[wid][2]=objc; sred[wid][3]=clsl; }
    __syncthreads();
    if (wid == 0) {
        float v0 = (lane < 8) ? sred[lane][0] : 0.f;
        float v1 = (lane < 8) ? sred[lane][1] : 0.f;
        float v2 = (lane < 8) ? sred[lane][2] : 0.f;
        float v3 = (lane < 8) ? sred[lane][3] : 0.f;
        #pragma unroll
        for (int o = 4; o > 0; o >>= 1) {
            v0 += __shfl_down_sync(0xffffffffu, v0, o);
            v1 += __shfl_down_sync(0xffffffffu, v1, o);
            v2 += __shfl_down_sync(0xffffffffu, v2, o);
            v3 += __shfl_down_sync(0xffffffffu, v3, o);
        }
        if (lane == 0) {
            int pb = b * KCBX + blockIdx.x;
            g_pA[0][pb]=v0; g_pA[1][pb]=v1; g_pA[2][pb]=v2; g_pA[3][pb]=v3;
        }
    }
}

// ===== kB: noobj loss with 2D tiles + safe GT pruning; final reduce =====
__global__ void __launch_bounds__(KBT) kB(const float* __restrict__ preds,
                                          const float* __restrict__ anchors,
                                          float* __restrict__ out, int B) {
    __shared__ float4 sbox[MAXGT];
    __shared__ float  scadd[MAXGT];
    __shared__ float  sanch[6];
    __shared__ int    scand;
    __shared__ float  sred[6];

    int b    = blockIdx.y;
    int tile = blockIdx.x;
    int tx0  = (tile % TILES) * TX;
    int ty0  = (tile / TILES) * TY;
    int tid  = threadIdx.x;
    int lane = tid & 31, wid = tid >> 5;

    if (tid == 0) scand = 0;
    if (tid < 6)  sanch[tid] = anchors[tid];
    __syncthreads();

    int cnt = min(g_cnt[b], MAXGT);
    if (tid < cnt) {
        float4 g = g_gt[b][tid];
        float x_lo = tx0 * 8.0f;
        float x_hi = (float)min(tx0 + TX, GSZ) * 8.0f;
        float y_lo = ty0 * 8.0f;
        float y_hi = (float)min(ty0 + TY, GSZ) * 8.0f;
        // necessary condition for IoU>=0.6: |bx-gx| <= gw/3, |by-gy| <= gh/3
        float mx = 0.35f * g.z + 0.02f;
        float my = 0.35f * g.w + 0.02f;
        if (g.x >= x_lo - mx && g.x <= x_hi + mx &&
            g.y >= y_lo - my && g.y <= y_hi + my) {
            int pos = atomicAdd(&scand, 1);
            sbox[pos]  = make_float4(g.x - 0.5f*g.z, g.y - 0.5f*g.w,
                                     g.x + 0.5f*g.z, g.y + 0.5f*g.w);
            scadd[pos] = 0.375f * (g.z * g.w + 1e-9f);
        }
    }
    __syncthreads();
    int ncand = scand;

    float contrib = 0.0f;
    int cell = tid / 3, a = tid - cell * 3;
    int cx = tx0 + (cell & 7);
    int cy = ty0 + (cell >> 3);

    if (cx < GSZ && cy < GSZ) {
        int n = (cy * GSZ + cx) * 3 + a;
        unsigned w = g_mask[b * 256 + (n >> 5)];
        if (!((w >> (n & 31)) & 1u)) {
            size_t rec = (size_t)b * NCELL + n;
            int k = (int)(rec & 3);
            size_t f  = rec * (size_t)REC;
            size_t a4 = (f - k) >> 2;
            float4 v0 = __ldg((const float4*)preds + a4);
            float4 v1 = __ldg((const float4*)preds + a4 + 1);
            float p5[5];
            select5(k, v0, v1, p5);

            float bx = (sigmoidf_(p5[0]) + (float)cx) * RATIO;
            float by = (sigmoidf_(p5[1]) + (float)cy) * RATIO;
            float bw = expf(p5[2]) * sanch[a * 2 + 0];
            float bh = expf(p5[3]) * sanch[a * 2 + 1];

            float px0 = bx - bw * 0.5f, px1 = bx + bw * 0.5f;
            float py0 = by - bh * 0.5f, py1 = by + bh * 0.5f;
            float apq = 0.375f * (bw * bh);

            bool hit = false;
            for (int i = 0; i < ncand; i++) {
                float4 g = sbox[i];
                float iw = fmaxf(fminf(px1, g.z) - fmaxf(px0, g.x), 0.0f);
                float ih = fmaxf(fminf(py1, g.w) - fmaxf(py0, g.y), 0.0f);
                float inter = iw * ih;
                // iou >= 0.6  <=>  inter >= 0.375*(ap + ag + 1e-9)
                hit = hit | (inter >= apq + scadd[i]);
            }
            if (!hit) contrib = softplusf(p5[4]);   // conf_t == 0 here
        }
    }

    // block reduce (6 warps)
    contrib = warpRedF(contrib);
    if (lane == 0) sred[wid] = contrib;
    __syncthreads();
    if (wid == 0) {
        float v = (lane < 6) ? sred[lane] : 0.f;
        #pragma unroll
        for (int o = 4; o > 0; o >>= 1) v += __shfl_down_sync(0xffffffffu, v, o);
        if (lane == 0) g_pB[b * NTILE + tile] = v;
    }

    // ---- last-block final reduction ----
    __threadfence();
    __shared__ bool amLast;
    if (tid == 0) {
        unsigned v = atomicAdd(&g_done, 1u);
        amLast = (v == (unsigned)(NTILE * gridDim.y) - 1u);
    }
    __syncthreads();
    if (!amLast) return;

    double s0=0, s1=0, s2=0, s3=0, s4=0;
    for (int i = tid; i < NTILE * B; i += KBT) s2 += (double)g_pB[i];
    for (int i = tid; i < KCBX * B; i += KBT) {
        s0 += (double)g_pA[0][i];
        s1 += (double)g_pA[1][i];
        s3 += (double)g_pA[2][i];
        s4 += (double)g_pA[3][i];
    }
    __shared__ double sw[6];
    double vals[5] = {s0, s1, s2, s3, s4};
    double res[5];
    #pragma unroll
    for (int j = 0; j < 5; j++) {
        double v = vals[j];
        #pragma unroll
        for (int o = 16; o > 0; o >>= 1) v += __shfl_down_sync(0xffffffffu, v, o);
        if (lane == 0) sw[wid] = v;
        __syncthreads();
        v = (tid < 6) ? sw[tid] : 0.0;
        if (wid == 0) {
            #pragma unroll
            for (int o = 4; o > 0; o >>= 1) v += __shfl_down_sync(0xffffffffu, v, o);
        }
        res[j] = v;
        __syncthreads();
    }
    if (tid == 0) {
        float v0 = (float)(res[0] / (double)B);
        float v1 = (float)(res[1] / (double)B);
        float v2 = (float)(res[2] / (double)B);
        float v3 = (float)(res[3] / (double)B);
        float v4 = (float)(res[4] / (double)B);
        out[0]=v0; out[1]=v1; out[2]=v2; out[3]=v3; out[4]=v4;
        out[5] = (((v0 + v1) + v2) + v3) + v4;
        g_done = 0;
    }
    if (tid < MAXB) g_cnt[tid] = 0;
}

extern "C" void kernel_launch(void* const* d_in, const int* in_sizes, int n_in,
                              void* d_out, int out_size) {
    const float* preds   = (const float*)d_in[0];
    const float* targets = (const float*)d_in[1];
    const float* anchors = (const float*)d_in[2];
    float* out = (float*)d_out;

    int B = in_sizes[0] / (NCELL * REC);
    if (B > MAXB) B = MAXB;

    dim3 gA(BPB, B);
    kA<<<gA, 256>>>(targets);
    dim3 gC(KCBX, B);
    kC<<<gC, 256>>>(preds, targets, anchors);
    dim3 gB(NTILE, B);
    kB<<<gB, KBT>>>(preds, anchors, out, B);
}